// round 1
// baseline (speedup 1.0000x reference)
#include <cuda_runtime.h>
#include <math.h>

#define BATCH 32
#define LSEQ  2000
#define DIM   1024
#define KEEP  500
#define MROWS (BATCH*KEEP)   // 16000
#define NMASK (BATCH*(LSEQ-KEEP))  // 48000
#define LN_EPS 1e-5f

// -------- scratch (device globals; no runtime allocation allowed) --------
__device__ int   g_rank[BATCH*LSEQ];
__device__ int   g_keep[BATCH*KEEP];
__device__ float g_latA[MROWS*DIM];     // latent rows for kept tokens (GEMM A)
__device__ float g_xd[MROWS*DIM];       // decoder output rows
__device__ float g_s[MROWS+1];          // per-row pred scalar; [MROWS] = mask_token pred
__device__ float g_losspart[BATCH];

// ===================== Kernel 1: stable ranks of noise =====================
// grid (BATCH, 8), block 256. Each block ranks 250 positions of one row.
__global__ void rank_kernel(const float* __restrict__ noise)
{
    __shared__ float sh[LSEQ];
    const int b = blockIdx.x;
    const float* nrow = noise + b*LSEQ;
    for (int i = threadIdx.x; i < LSEQ; i += blockDim.x) sh[i] = nrow[i];
    __syncthreads();

    const int j = blockIdx.y*250 + threadIdx.x;
    if (threadIdx.x >= 250) return;
    const float nj = sh[j];
    int r = 0;
    #pragma unroll 4
    for (int k = 0; k < LSEQ; ++k) {
        float nk = sh[k];
        r += (nk < nj) || (nk == nj && k < j);   // stable argsort rank
    }
    g_rank[b*LSEQ + j] = r;
    if (r < KEEP) g_keep[b*KEEP + r] = j;        // ids_shuffle[r] = j
}

// ============ Kernel 2: gather + encode + LayerNorm1 -> latent ============
// grid (KEEP+1, BATCH), block 256, 4 elems/thread.
__global__ void enc_ln_kernel(const float* __restrict__ expr,
                              const int*   __restrict__ idx,
                              const float* __restrict__ pos,
                              const float* __restrict__ cls,
                              const float* __restrict__ w_enc,
                              const float* __restrict__ b_enc,
                              const float* __restrict__ g1,
                              const float* __restrict__ be1,
                              float* __restrict__ out_lat0)
{
    const int t = blockIdx.x, b = blockIdx.y, tid = threadIdx.x;
    float v[4];
    if (t == 0) {
        #pragma unroll
        for (int i = 0; i < 4; ++i) { int d = tid + i*256; v[i] = cls[d] + pos[d]; }
    } else {
        const int j  = g_keep[b*KEEP + (t-1)];
        const float e = expr[b*LSEQ + j];
        const float* prow = pos + (size_t)idx[b*LSEQ + j] * DIM;
        #pragma unroll
        for (int i = 0; i < 4; ++i) { int d = tid + i*256; v[i] = e*w_enc[d] + b_enc[d] + prow[d]; }
    }

    __shared__ float red[256];
    float s = v[0]+v[1]+v[2]+v[3];
    red[tid] = s; __syncthreads();
    #pragma unroll
    for (int o = 128; o > 0; o >>= 1) { if (tid < o) red[tid] += red[tid+o]; __syncthreads(); }
    const float mean = red[0] * (1.0f/DIM);
    __syncthreads();

    float sv = 0.f;
    #pragma unroll
    for (int i = 0; i < 4; ++i) { float dv = v[i]-mean; sv += dv*dv; }
    red[tid] = sv; __syncthreads();
    #pragma unroll
    for (int o = 128; o > 0; o >>= 1) { if (tid < o) red[tid] += red[tid+o]; __syncthreads(); }
    const float inv = rsqrtf(red[0]*(1.0f/DIM) + LN_EPS);

    float* dst = (t == 0) ? (out_lat0 + b*DIM)
                          : (g_latA + (size_t)(b*KEEP + (t-1))*DIM);
    #pragma unroll
    for (int i = 0; i < 4; ++i) { int d = tid + i*256; dst[d] = (v[i]-mean)*inv*g1[d] + be1[d]; }
}

// ============ Kernel 3: SGEMM  xd = latA(16000x1024) @ W_dec + b_dec ============
// 128x128 tile, BK=8, 256 threads, 8x8 per thread. grid (8, 125).
__global__ void __launch_bounds__(256)
gemm_kernel(const float* __restrict__ Wd, const float* __restrict__ bias)
{
    __shared__ float As[8][128];
    __shared__ float Bs[8][128];

    const int bn = blockIdx.x * 128;
    const int bm = blockIdx.y * 128;
    const int tid = threadIdx.x;
    const int tx = tid & 15, ty = tid >> 4;

    const int arow = tid >> 1;            // 0..127
    const int acol = (tid & 1) * 4;       // 0 or 4
    const int brow = tid >> 5;            // 0..7
    const int bcol = (tid & 31) * 4;

    float acc[8][8] = {};
    const float* Abase = g_latA + (size_t)(bm + arow)*DIM + acol;
    const float* Bbase = Wd + (size_t)brow*DIM + bn + bcol;

    for (int k0 = 0; k0 < DIM; k0 += 8) {
        float4 a4 = *(const float4*)(Abase + k0);
        As[acol+0][arow] = a4.x; As[acol+1][arow] = a4.y;
        As[acol+2][arow] = a4.z; As[acol+3][arow] = a4.w;
        *(float4*)&Bs[brow][bcol] = *(const float4*)(Bbase + (size_t)k0*DIM);
        __syncthreads();

        #pragma unroll
        for (int k = 0; k < 8; ++k) {
            float4 a0 = *(const float4*)&As[k][ty*8];
            float4 a1 = *(const float4*)&As[k][ty*8+4];
            float4 b0 = *(const float4*)&Bs[k][tx*8];
            float4 b1 = *(const float4*)&Bs[k][tx*8+4];
            float af[8] = {a0.x,a0.y,a0.z,a0.w,a1.x,a1.y,a1.z,a1.w};
            float bf[8] = {b0.x,b0.y,b0.z,b0.w,b1.x,b1.y,b1.z,b1.w};
            #pragma unroll
            for (int i = 0; i < 8; ++i)
                #pragma unroll
                for (int j = 0; j < 8; ++j)
                    acc[i][j] += af[i]*bf[j];
        }
        __syncthreads();
    }

    #pragma unroll
    for (int i = 0; i < 8; ++i) {
        const int m = bm + ty*8 + i;
        float* orow = g_xd + (size_t)m*DIM + bn + tx*8;
        #pragma unroll
        for (int j = 0; j < 8; j += 4) {
            const int n = bn + tx*8 + j;
            float4 o;
            o.x = acc[i][j+0] + bias[n+0];
            o.y = acc[i][j+1] + bias[n+1];
            o.z = acc[i][j+2] + bias[n+2];
            o.w = acc[i][j+3] + bias[n+3];
            *(float4*)(orow + j) = o;
        }
    }
}

// ============ Kernel 4: LayerNorm2 + dot(W_pred) per row ============
// grid MROWS+1 (last row = mask_token), block 256.
__global__ void ln2_dot_kernel(const float* __restrict__ mask_token,
                               const float* __restrict__ g2,
                               const float* __restrict__ be2,
                               const float* __restrict__ Wp,
                               const float* __restrict__ bp)
{
    const int row = blockIdx.x, tid = threadIdx.x;
    const float* src = (row < MROWS) ? (g_xd + (size_t)row*DIM) : mask_token;

    float v[4];
    #pragma unroll
    for (int i = 0; i < 4; ++i) v[i] = src[tid + i*256];

    __shared__ float red[256];
    float s = v[0]+v[1]+v[2]+v[3];
    red[tid] = s; __syncthreads();
    #pragma unroll
    for (int o = 128; o > 0; o >>= 1) { if (tid < o) red[tid] += red[tid+o]; __syncthreads(); }
    const float mean = red[0] * (1.0f/DIM);
    __syncthreads();

    float sv = 0.f;
    #pragma unroll
    for (int i = 0; i < 4; ++i) { float dv = v[i]-mean; sv += dv*dv; }
    red[tid] = sv; __syncthreads();
    #pragma unroll
    for (int o = 128; o > 0; o >>= 1) { if (tid < o) red[tid] += red[tid+o]; __syncthreads(); }
    const float inv = rsqrtf(red[0]*(1.0f/DIM) + LN_EPS);
    __syncthreads();

    float part = 0.f;
    #pragma unroll
    for (int i = 0; i < 4; ++i) {
        int d = tid + i*256;
        part += ((v[i]-mean)*inv*g2[d] + be2[d]) * Wp[d];
    }
    red[tid] = part; __syncthreads();
    #pragma unroll
    for (int o = 128; o > 0; o >>= 1) { if (tid < o) red[tid] += red[tid+o]; __syncthreads(); }
    if (tid == 0) g_s[row] = red[0] + bp[0];
}

// ============ Kernel 5: scatter pred/mask + per-batch loss partial ============
__global__ void out_kernel(const float* __restrict__ expr,
                           float* __restrict__ out_pred,
                           float* __restrict__ out_mask)
{
    const int b = blockIdx.x;
    const float cm = g_s[MROWS];
    float part = 0.f;
    for (int l = threadIdx.x; l < LSEQ; l += blockDim.x) {
        const int r = g_rank[b*LSEQ + l];
        const bool masked = (r >= KEEP);
        const float p = masked ? cm : g_s[b*KEEP + r];
        out_pred[b*LSEQ + l] = p;
        out_mask[b*LSEQ + l] = masked ? 1.0f : 0.0f;
        if (masked) {
            float t = expr[b*LSEQ + l];
            if (isnan(t)) t = 0.f;     // nan_to_num
            const float d = p - t;
            part += d*d;
        }
    }
    __shared__ float red[256];
    red[threadIdx.x] = part; __syncthreads();
    #pragma unroll
    for (int o = 128; o > 0; o >>= 1) { if (threadIdx.x < o) red[threadIdx.x] += red[threadIdx.x+o]; __syncthreads(); }
    if (threadIdx.x == 0) g_losspart[b] = red[0];
}

// ============ Kernel 6: final deterministic loss reduction ============
__global__ void loss_kernel(float* __restrict__ out)
{
    if (threadIdx.x == 0) {
        float s = 0.f;
        for (int i = 0; i < BATCH; ++i) s += g_losspart[i];
        out[0] = s / (float)NMASK;
    }
}

// =============================== launch ===============================
extern "C" void kernel_launch(void* const* d_in, const int* in_sizes, int n_in,
                              void* d_out, int out_size)
{
    const float* expr      = (const float*)d_in[0];
    const int*   idx       = (const int*)  d_in[1];
    const float* noise     = (const float*)d_in[2];
    const float* pos_table = (const float*)d_in[3];
    const float* cls_token = (const float*)d_in[4];
    const float* w_enc     = (const float*)d_in[5];
    const float* b_enc     = (const float*)d_in[6];
    const float* gamma1    = (const float*)d_in[7];
    const float* beta1     = (const float*)d_in[8];
    const float* W_dec     = (const float*)d_in[9];
    const float* b_dec     = (const float*)d_in[10];
    const float* mask_tok  = (const float*)d_in[11];
    const float* gamma2    = (const float*)d_in[12];
    const float* beta2     = (const float*)d_in[13];
    const float* W_pred    = (const float*)d_in[14];
    const float* b_pred    = (const float*)d_in[15];

    float* out = (float*)d_out;
    float* out_loss  = out;                       // [1]
    float* out_pred  = out + 1;                   // [B*L]
    float* out_mask  = out + 1 + BATCH*LSEQ;      // [B*L]
    float* out_lat0  = out + 1 + 2*BATCH*LSEQ;    // [B*D]

    rank_kernel<<<dim3(BATCH, 8), 256>>>(noise);
    enc_ln_kernel<<<dim3(KEEP+1, BATCH), 256>>>(expr, idx, pos_table, cls_token,
                                                w_enc, b_enc, gamma1, beta1, out_lat0);
    gemm_kernel<<<dim3(DIM/128, MROWS/128), 256>>>(W_dec, b_dec);
    ln2_dot_kernel<<<MROWS+1, 256>>>(mask_tok, gamma2, beta2, W_pred, b_pred);
    out_kernel<<<BATCH, 256>>>(expr, out_pred, out_mask);
    loss_kernel<<<1, 32>>>(out_loss);
}

// round 3
// speedup vs baseline: 2.1553x; 2.1553x over previous
#include <cuda_runtime.h>
#include <cuda_bf16.h>
#include <math.h>
#include <stdint.h>

#define BATCH 32
#define LSEQ  2000
#define DIM   1024
#define KEEP  500
#define MROWS (BATCH*KEEP)           // 16000
#define NMASK (BATCH*(LSEQ-KEEP))    // 48000
#define LN_EPS 1e-5f

// GEMM tiling
#define MT 128
#define NT 256
#define KC 32                         // K per stage (bf16 elems)
#define NSTAGE (DIM/KC)               // 32
#define ROWB 80                       // padded smem row bytes (40 halfs)
#define A_SPLIT_B (MT*ROWB)           // 10240
#define B_SPLIT_B (NT*ROWB)           // 20480
#define STAGE_B (2*A_SPLIT_B + 2*B_SPLIT_B)   // 61440
#define SMEM_TOTAL (3*STAGE_B)        // 184320

// -------- scratch (device globals; no runtime allocation allowed) --------
__device__ int   g_rank[BATCH*LSEQ];
__device__ int   g_keep[BATCH*KEEP];
__device__ __align__(16) __nv_bfloat16 g_Ahi[MROWS*DIM];
__device__ __align__(16) __nv_bfloat16 g_Alo[MROWS*DIM];
__device__ __align__(16) __nv_bfloat16 g_Bhi[DIM*DIM];   // [n][k] = W_dec[k][n]
__device__ __align__(16) __nv_bfloat16 g_Blo[DIM*DIM];
__device__ __align__(16) float g_xd[MROWS*DIM];
__device__ float g_s[MROWS+1];
__device__ float g_losspart[BATCH];

// =============================== PTX helpers ===============================
__device__ __forceinline__ uint32_t s2u(const void* p) {
    uint32_t a;
    asm("{ .reg .u64 t; cvta.to.shared.u64 t, %1; cvt.u32.u64 %0, t; }" : "=r"(a) : "l"(p));
    return a;
}
__device__ __forceinline__ void cp16(uint32_t s, const void* g) {
    asm volatile("cp.async.cg.shared.global [%0], [%1], 16;" :: "r"(s), "l"(g) : "memory");
}
__device__ __forceinline__ void ldm4(uint32_t* r, uint32_t addr) {
    asm volatile("ldmatrix.sync.aligned.m8n8.x4.shared.b16 {%0,%1,%2,%3}, [%4];"
                 : "=r"(r[0]), "=r"(r[1]), "=r"(r[2]), "=r"(r[3]) : "r"(addr));
}
__device__ __forceinline__ void mma16816(float* c, const uint32_t* a, const uint32_t* b) {
    asm volatile(
        "mma.sync.aligned.m16n8k16.row.col.f32.bf16.bf16.f32 "
        "{%0,%1,%2,%3}, {%4,%5,%6,%7}, {%8,%9}, {%0,%1,%2,%3};"
        : "+f"(c[0]), "+f"(c[1]), "+f"(c[2]), "+f"(c[3])
        : "r"(a[0]), "r"(a[1]), "r"(a[2]), "r"(a[3]), "r"(b[0]), "r"(b[1]));
}

// ===================== Kernel 1: stable ranks of noise =====================
__global__ void rank_kernel(const float* __restrict__ noise)
{
    __shared__ float sh[LSEQ];
    const int b = blockIdx.x;
    const float* nrow = noise + b*LSEQ;
    for (int i = threadIdx.x; i < LSEQ; i += blockDim.x) sh[i] = nrow[i];
    __syncthreads();

    const int j = blockIdx.y*250 + threadIdx.x;
    if (threadIdx.x >= 250) return;
    const float nj = sh[j];
    int r = 0;
    #pragma unroll 4
    for (int k = 0; k < LSEQ; ++k) {
        float nk = sh[k];
        r += (nk < nj) || (nk == nj && k < j);
    }
    g_rank[b*LSEQ + j] = r;
    if (r < KEEP) g_keep[b*KEEP + r] = j;
}

// ===== Kernel 2: gather + encode + LayerNorm1 -> bf16 split A (+latent0) =====
__global__ void enc_ln_kernel(const float* __restrict__ expr,
                              const int*   __restrict__ idx,
                              const float* __restrict__ pos,
                              const float* __restrict__ cls,
                              const float* __restrict__ w_enc,
                              const float* __restrict__ b_enc,
                              const float* __restrict__ g1,
                              const float* __restrict__ be1,
                              float* __restrict__ out_lat0)
{
    const int t = blockIdx.x, b = blockIdx.y, tid = threadIdx.x;
    float v[4];
    if (t == 0) {
        #pragma unroll
        for (int i = 0; i < 4; ++i) { int d = tid + i*256; v[i] = cls[d] + pos[d]; }
    } else {
        const int j  = g_keep[b*KEEP + (t-1)];
        const float e = expr[b*LSEQ + j];
        const float* prow = pos + (size_t)idx[b*LSEQ + j] * DIM;
        #pragma unroll
        for (int i = 0; i < 4; ++i) { int d = tid + i*256; v[i] = e*w_enc[d] + b_enc[d] + prow[d]; }
    }

    __shared__ float red[256];
    float s = v[0]+v[1]+v[2]+v[3];
    red[tid] = s; __syncthreads();
    #pragma unroll
    for (int o = 128; o > 0; o >>= 1) { if (tid < o) red[tid] += red[tid+o]; __syncthreads(); }
    const float mean = red[0] * (1.0f/DIM);
    __syncthreads();

    float sv = 0.f;
    #pragma unroll
    for (int i = 0; i < 4; ++i) { float dv = v[i]-mean; sv += dv*dv; }
    red[tid] = sv; __syncthreads();
    #pragma unroll
    for (int o = 128; o > 0; o >>= 1) { if (tid < o) red[tid] += red[tid+o]; __syncthreads(); }
    const float inv = rsqrtf(red[0]*(1.0f/DIM) + LN_EPS);

    if (t == 0) {
        float* dst = out_lat0 + b*DIM;
        #pragma unroll
        for (int i = 0; i < 4; ++i) { int d = tid + i*256; dst[d] = (v[i]-mean)*inv*g1[d] + be1[d]; }
    } else {
        const size_t row = (size_t)(b*KEEP + (t-1))*DIM;
        #pragma unroll
        for (int i = 0; i < 4; ++i) {
            int d = tid + i*256;
            float val = (v[i]-mean)*inv*g1[d] + be1[d];
            __nv_bfloat16 h = __float2bfloat16(val);
            g_Ahi[row + d] = h;
            g_Alo[row + d] = __float2bfloat16(val - __bfloat162float(h));
        }
    }
}

// ========= Kernel 2b: transpose + bf16-split W_dec -> g_Bhi/g_Blo =========
__global__ void prep_b_kernel(const float* __restrict__ Wd)
{
    __shared__ float t[32][33];
    const int tx = threadIdx.x, ty = threadIdx.y;
    const int bx = blockIdx.x, by = blockIdx.y;
    #pragma unroll
    for (int j = 0; j < 32; j += 8)
        t[ty+j][tx] = Wd[(size_t)(by*32 + ty + j)*DIM + bx*32 + tx];
    __syncthreads();
    #pragma unroll
    for (int j = 0; j < 32; j += 8) {
        float v = t[tx][ty+j];                       // = W_dec[by*32+tx][bx*32+ty+j]
        size_t o = (size_t)(bx*32 + ty + j)*DIM + by*32 + tx;  // [n][k]
        __nv_bfloat16 h = __float2bfloat16(v);
        g_Bhi[o] = h;
        g_Blo[o] = __float2bfloat16(v - __bfloat162float(h));
    }
}

// ====== Kernel 3: HMMA split-bf16 GEMM  xd = latA @ W_dec + b_dec ======
__device__ __forceinline__ void load_stage(uint32_t sb, int stage, int bm, int bn, int tid)
{
    const uint32_t st = sb + (uint32_t)(stage % 3) * STAGE_B;
    const int kbase = stage * KC;
    // 3072 16B chunks: A hi/lo 1024, B hi/lo 2048
    #pragma unroll
    for (int i = 0; i < 12; ++i) {
        const int id = i*256 + tid;
        if (id < 1024) {
            const int split = id >> 9, t = id & 511, r = t >> 2, seg = t & 3;
            const __nv_bfloat16* src = (split ? g_Alo : g_Ahi)
                                     + (size_t)(bm + r)*DIM + kbase + seg*8;
            cp16(st + (uint32_t)(split*A_SPLIT_B + r*ROWB + seg*16), src);
        } else {
            const int id2 = id - 1024;
            const int split = id2 >> 10, t = id2 & 1023, r = t >> 2, seg = t & 3;
            const __nv_bfloat16* src = (split ? g_Blo : g_Bhi)
                                     + (size_t)(bn + r)*DIM + kbase + seg*8;
            cp16(st + (uint32_t)(2*A_SPLIT_B + split*B_SPLIT_B + r*ROWB + seg*16), src);
        }
    }
    asm volatile("cp.async.commit_group;" ::: "memory");
}

__global__ void __launch_bounds__(256, 1)
gemm_tc_kernel(const float* __restrict__ bias)
{
    extern __shared__ char sm_[];
    const uint32_t sb = s2u(sm_);
    const int tid = threadIdx.x, wid = tid >> 5, lane = tid & 31;
    const int bn = blockIdx.x * NT, bm = blockIdx.y * MT;
    const int wm = wid >> 2, wn = wid & 3;      // warp tile 64x64

    float acc[4][8][4] = {};

    load_stage(sb, 0, bm, bn, tid);
    load_stage(sb, 1, bm, bn, tid);

    // per-lane fixed components of ldmatrix addresses
    const uint32_t aOff = (uint32_t)((wm*64 + (lane & 15))*ROWB + (lane >> 4)*16);
    const uint32_t bOff = (uint32_t)(2*A_SPLIT_B
                       + (wn*64 + (lane & 7) + (lane >> 4)*8)*ROWB
                       + ((lane >> 3) & 1)*16);

    for (int s = 0; s < NSTAGE; ++s) {
        asm volatile("cp.async.wait_group 1;" ::: "memory");
        __syncthreads();
        if (s + 2 < NSTAGE) load_stage(sb, s + 2, bm, bn, tid);

        const uint32_t st = sb + (uint32_t)(s % 3) * STAGE_B;
        #pragma unroll
        for (int ks = 0; ks < 2; ++ks) {
            const uint32_t kb = (uint32_t)(ks*32);
            uint32_t Ah[4][4], Bh[4][4], T[4][4];
            #pragma unroll
            for (int mi = 0; mi < 4; ++mi)
                ldm4(Ah[mi], st + aOff + (uint32_t)(mi*16*ROWB) + kb);
            #pragma unroll
            for (int np = 0; np < 4; ++np)
                ldm4(Bh[np], st + bOff + (uint32_t)(np*16*ROWB) + kb);
            // hi * hi
            #pragma unroll
            for (int mi = 0; mi < 4; ++mi)
                #pragma unroll
                for (int ni = 0; ni < 8; ++ni)
                    mma16816(acc[mi][ni], Ah[mi], &Bh[ni>>1][(ni&1)*2]);
            // hi * lo  (B_lo)
            #pragma unroll
            for (int np = 0; np < 4; ++np)
                ldm4(T[np], st + bOff + (uint32_t)(B_SPLIT_B + np*16*ROWB) + kb);
            #pragma unroll
            for (int mi = 0; mi < 4; ++mi)
                #pragma unroll
                for (int ni = 0; ni < 8; ++ni)
                    mma16816(acc[mi][ni], Ah[mi], &T[ni>>1][(ni&1)*2]);
            // lo * hi  (A_lo)
            #pragma unroll
            for (int mi = 0; mi < 4; ++mi)
                ldm4(T[mi], st + aOff + (uint32_t)(A_SPLIT_B + mi*16*ROWB) + kb);
            #pragma unroll
            for (int mi = 0; mi < 4; ++mi)
                #pragma unroll
                for (int ni = 0; ni < 8; ++ni)
                    mma16816(acc[mi][ni], T[mi], &Bh[ni>>1][(ni&1)*2]);
        }
    }

    // epilogue: add bias, store fp32
    const int r4 = lane >> 2, c2 = (lane & 3)*2;
    #pragma unroll
    for (int ni = 0; ni < 8; ++ni) {
        const int n = bn + wn*64 + ni*8 + c2;
        const float2 bv = *(const float2*)(bias + n);
        #pragma unroll
        for (int mi = 0; mi < 4; ++mi) {
            const int m0 = bm + wm*64 + mi*16 + r4;
            float* p = g_xd + (size_t)m0*DIM + n;
            float2 o0 = { acc[mi][ni][0] + bv.x, acc[mi][ni][1] + bv.y };
            *(float2*)p = o0;
            float2 o1 = { acc[mi][ni][2] + bv.x, acc[mi][ni][3] + bv.y };
            *(float2*)(p + 8*DIM) = o1;
        }
    }
}

// ===== Kernel 4: LayerNorm2 + dot(W_pred), warp per row =====
__global__ void ln2_dot_kernel(const float* __restrict__ mask_token,
                               const float* __restrict__ g2,
                               const float* __restrict__ be2,
                               const float* __restrict__ Wp,
                               const float* __restrict__ bp)
{
    const int w = blockIdx.x*8 + (threadIdx.x >> 5);
    if (w > MROWS) return;
    const int lane = threadIdx.x & 31;
    const float* src = (w < MROWS) ? (g_xd + (size_t)w*DIM) : mask_token;

    float4 v[8];
    float s = 0.f, sq = 0.f;
    #pragma unroll
    for (int i = 0; i < 8; ++i) {
        v[i] = ((const float4*)src)[lane + i*32];
        s  += v[i].x + v[i].y + v[i].z + v[i].w;
        sq += v[i].x*v[i].x + v[i].y*v[i].y + v[i].z*v[i].z + v[i].w*v[i].w;
    }
    #pragma unroll
    for (int o = 16; o; o >>= 1) {
        s  += __shfl_xor_sync(0xFFFFFFFFu, s,  o);
        sq += __shfl_xor_sync(0xFFFFFFFFu, sq, o);
    }
    const float mean = s * (1.0f/DIM);
    const float var  = sq * (1.0f/DIM) - mean*mean;
    const float inv  = rsqrtf(var + LN_EPS);

    float part = 0.f;
    #pragma unroll
    for (int i = 0; i < 8; ++i) {
        const int e = lane + i*32;
        float4 g  = ((const float4*)g2)[e];
        float4 be = ((const float4*)be2)[e];
        float4 wp = ((const float4*)Wp)[e];
        part += ((v[i].x - mean)*inv*g.x + be.x) * wp.x;
        part += ((v[i].y - mean)*inv*g.y + be.y) * wp.y;
        part += ((v[i].z - mean)*inv*g.z + be.z) * wp.z;
        part += ((v[i].w - mean)*inv*g.w + be.w) * wp.w;
    }
    #pragma unroll
    for (int o = 16; o; o >>= 1) part += __shfl_xor_sync(0xFFFFFFFFu, part, o);
    if (lane == 0) g_s[w] = part + bp[0];
}

// ===== Kernel 5: scatter pred/mask + per-batch loss partial =====
__global__ void out_kernel(const float* __restrict__ expr,
                           float* __restrict__ out_pred,
                           float* __restrict__ out_mask)
{
    const int b = blockIdx.x;
    const float cm = g_s[MROWS];
    float part = 0.f;
    for (int l = threadIdx.x; l < LSEQ; l += blockDim.x) {
        const int r = g_rank[b*LSEQ + l];
        const bool masked = (r >= KEEP);
        const float p = masked ? cm : g_s[b*KEEP + r];
        out_pred[b*LSEQ + l] = p;
        out_mask[b*LSEQ + l] = masked ? 1.0f : 0.0f;
        if (masked) {
            float t = expr[b*LSEQ + l];
            if (isnan(t)) t = 0.f;
            const float d = p - t;
            part += d*d;
        }
    }
    __shared__ float red[256];
    red[threadIdx.x] = part; __syncthreads();
    #pragma unroll
    for (int o = 128; o > 0; o >>= 1) {
        if (threadIdx.x < o) red[threadIdx.x] += red[threadIdx.x+o];
        __syncthreads();
    }
    if (threadIdx.x == 0) g_losspart[b] = red[0];
}

// ===== Kernel 6: final deterministic loss reduction =====
__global__ void loss_kernel(float* __restrict__ out)
{
    if (threadIdx.x == 0) {
        float s = 0.f;
        for (int i = 0; i < BATCH; ++i) s += g_losspart[i];
        out[0] = s / (float)NMASK;
    }
}

// =============================== launch ===============================
extern "C" void kernel_launch(void* const* d_in, const int* in_sizes, int n_in,
                              void* d_out, int out_size)
{
    const float* expr      = (const float*)d_in[0];
    const int*   idx       = (const int*)  d_in[1];
    const float* noise     = (const float*)d_in[2];
    const float* pos_table = (const float*)d_in[3];
    const float* cls_token = (const float*)d_in[4];
    const float* w_enc     = (const float*)d_in[5];
    const float* b_enc     = (const float*)d_in[6];
    const float* gamma1    = (const float*)d_in[7];
    const float* beta1     = (const float*)d_in[8];
    const float* W_dec     = (const float*)d_in[9];
    const float* b_dec     = (const float*)d_in[10];
    const float* mask_tok  = (const float*)d_in[11];
    const float* gamma2    = (const float*)d_in[12];
    const float* beta2     = (const float*)d_in[13];
    const float* W_pred    = (const float*)d_in[14];
    const float* b_pred    = (const float*)d_in[15];

    float* out = (float*)d_out;
    float* out_loss  = out;
    float* out_pred  = out + 1;
    float* out_mask  = out + 1 + BATCH*LSEQ;
    float* out_lat0  = out + 1 + 2*BATCH*LSEQ;

    cudaFuncSetAttribute(gemm_tc_kernel,
                         cudaFuncAttributeMaxDynamicSharedMemorySize, SMEM_TOTAL);

    prep_b_kernel<<<dim3(32, 32), dim3(32, 8)>>>(W_dec);
    rank_kernel<<<dim3(BATCH, 8), 256>>>(noise);
    enc_ln_kernel<<<dim3(KEEP+1, BATCH), 256>>>(expr, idx, pos_table, cls_token,
                                                w_enc, b_enc, gamma1, beta1, out_lat0);
    gemm_tc_kernel<<<dim3(DIM/NT, MROWS/MT), 256, SMEM_TOTAL>>>(b_dec);
    ln2_dot_kernel<<<(MROWS + 8)/8, 256>>>(mask_tok, gamma2, beta2, W_pred, b_pred);
    out_kernel<<<BATCH, 256>>>(expr, out_pred, out_mask);
    loss_kernel<<<1, 32>>>(out_loss);
}

// round 4
// speedup vs baseline: 2.4694x; 1.1457x over previous
#include <cuda_runtime.h>
#include <cuda_bf16.h>
#include <math.h>
#include <stdint.h>

#define BATCH 32
#define LSEQ  2000
#define DIM   1024
#define KEEP  500
#define MROWS (BATCH*KEEP)           // 16000
#define NMASK (BATCH*(LSEQ-KEEP))    // 48000
#define LN_EPS 1e-5f

// GEMM tiling: CTA 128x128, warp 32x64 (4 M-groups x 2 N-groups), KC=32, 2 stages
#define MT 128
#define NT 128
#define KC 32
#define NSTAGE (DIM/KC)              // 32
#define ROWB 80                      // padded smem row bytes
#define SPLIT_B (128*ROWB)           // 10240
#define STAGE_B (4*SPLIT_B)          // 40960 (Ahi,Alo,Bhi,Blo)
#define SMEM_TOTAL (2*STAGE_B)       // 81920

// -------- scratch (device globals) --------
__device__ int   g_rank[BATCH*LSEQ];
__device__ int   g_keep[BATCH*KEEP];
__device__ __align__(16) __nv_bfloat16 g_Ahi[MROWS*DIM];
__device__ __align__(16) __nv_bfloat16 g_Alo[MROWS*DIM];
__device__ __align__(16) __nv_bfloat16 g_Bhi[DIM*DIM];   // [n][k] = W_dec[k][n]
__device__ __align__(16) __nv_bfloat16 g_Blo[DIM*DIM];
__device__ __align__(16) float g_gw[DIM];                // gamma2*W_pred
__device__ float g_consts[2];                            // {sum(g2*Wp), sum(be2*Wp)+bp}
__device__ float g_part[3*8*MROWS];                      // [stat][ntile][row]
__device__ float g_s[MROWS+1];
__device__ float g_losspart[BATCH];

// =============================== PTX helpers ===============================
__device__ __forceinline__ uint32_t s2u(const void* p) {
    uint32_t a;
    asm("{ .reg .u64 t; cvta.to.shared.u64 t, %1; cvt.u32.u64 %0, t; }" : "=r"(a) : "l"(p));
    return a;
}
__device__ __forceinline__ void cp16(uint32_t s, const void* g) {
    asm volatile("cp.async.cg.shared.global [%0], [%1], 16;" :: "r"(s), "l"(g) : "memory");
}
__device__ __forceinline__ void ldm4(uint32_t* r, uint32_t addr) {
    asm volatile("ldmatrix.sync.aligned.m8n8.x4.shared.b16 {%0,%1,%2,%3}, [%4];"
                 : "=r"(r[0]), "=r"(r[1]), "=r"(r[2]), "=r"(r[3]) : "r"(addr));
}
__device__ __forceinline__ void mma16816(float* c, const uint32_t* a, const uint32_t* b) {
    asm volatile(
        "mma.sync.aligned.m16n8k16.row.col.f32.bf16.bf16.f32 "
        "{%0,%1,%2,%3}, {%4,%5,%6,%7}, {%8,%9}, {%0,%1,%2,%3};"
        : "+f"(c[0]), "+f"(c[1]), "+f"(c[2]), "+f"(c[3])
        : "r"(a[0]), "r"(a[1]), "r"(a[2]), "r"(a[3]), "r"(b[0]), "r"(b[1]));
}

// ===================== Kernel 1: stable ranks of noise =====================
__global__ void rank_kernel(const float* __restrict__ noise)
{
    __shared__ float sh[LSEQ];
    const int b = blockIdx.x;
    const float* nrow = noise + b*LSEQ;
    for (int i = threadIdx.x; i < LSEQ; i += blockDim.x) sh[i] = nrow[i];
    __syncthreads();

    const int j = blockIdx.y*250 + threadIdx.x;
    if (threadIdx.x >= 250) return;
    const float nj = sh[j];
    int r = 0;
    #pragma unroll 4
    for (int k = 0; k < LSEQ; ++k) {
        float nk = sh[k];
        r += (nk < nj) || (nk == nj && k < j);
    }
    g_rank[b*LSEQ + j] = r;
    if (r < KEEP) g_keep[b*KEEP + r] = j;
}

// ===== Kernel 2: gather + encode + LayerNorm1 -> bf16 split A (+latent0) =====
__global__ void enc_ln_kernel(const float* __restrict__ expr,
                              const int*   __restrict__ idx,
                              const float* __restrict__ pos,
                              const float* __restrict__ cls,
                              const float* __restrict__ w_enc,
                              const float* __restrict__ b_enc,
                              const float* __restrict__ g1,
                              const float* __restrict__ be1,
                              float* __restrict__ out_lat0)
{
    const int t = blockIdx.x, b = blockIdx.y, tid = threadIdx.x;
    float v[4];
    if (t == 0) {
        #pragma unroll
        for (int i = 0; i < 4; ++i) { int d = tid + i*256; v[i] = cls[d] + pos[d]; }
    } else {
        const int j  = g_keep[b*KEEP + (t-1)];
        const float e = expr[b*LSEQ + j];
        const float* prow = pos + (size_t)idx[b*LSEQ + j] * DIM;
        #pragma unroll
        for (int i = 0; i < 4; ++i) { int d = tid + i*256; v[i] = e*w_enc[d] + b_enc[d] + prow[d]; }
    }

    __shared__ float red[256];
    float s = v[0]+v[1]+v[2]+v[3];
    red[tid] = s; __syncthreads();
    #pragma unroll
    for (int o = 128; o > 0; o >>= 1) { if (tid < o) red[tid] += red[tid+o]; __syncthreads(); }
    const float mean = red[0] * (1.0f/DIM);
    __syncthreads();

    float sv = 0.f;
    #pragma unroll
    for (int i = 0; i < 4; ++i) { float dv = v[i]-mean; sv += dv*dv; }
    red[tid] = sv; __syncthreads();
    #pragma unroll
    for (int o = 128; o > 0; o >>= 1) { if (tid < o) red[tid] += red[tid+o]; __syncthreads(); }
    const float inv = rsqrtf(red[0]*(1.0f/DIM) + LN_EPS);

    if (t == 0) {
        float* dst = out_lat0 + b*DIM;
        #pragma unroll
        for (int i = 0; i < 4; ++i) { int d = tid + i*256; dst[d] = (v[i]-mean)*inv*g1[d] + be1[d]; }
    } else {
        const size_t row = (size_t)(b*KEEP + (t-1))*DIM;
        #pragma unroll
        for (int i = 0; i < 4; ++i) {
            int d = tid + i*256;
            float val = (v[i]-mean)*inv*g1[d] + be1[d];
            __nv_bfloat16 h = __float2bfloat16(val);
            g_Ahi[row + d] = h;
            g_Alo[row + d] = __float2bfloat16(val - __bfloat162float(h));
        }
    }
}

// ========= Kernel 2b: transpose + bf16-split W_dec =========
__global__ void prep_b_kernel(const float* __restrict__ Wd)
{
    __shared__ float t[32][33];
    const int tx = threadIdx.x, ty = threadIdx.y;
    const int bx = blockIdx.x, by = blockIdx.y;
    #pragma unroll
    for (int j = 0; j < 32; j += 8)
        t[ty+j][tx] = Wd[(size_t)(by*32 + ty + j)*DIM + bx*32 + tx];
    __syncthreads();
    #pragma unroll
    for (int j = 0; j < 32; j += 8) {
        float v = t[tx][ty+j];
        size_t o = (size_t)(bx*32 + ty + j)*DIM + by*32 + tx;  // [n][k]
        __nv_bfloat16 h = __float2bfloat16(v);
        g_Bhi[o] = h;
        g_Blo[o] = __float2bfloat16(v - __bfloat162float(h));
    }
}

// ========= Kernel 2c: gw = g2*Wp, consts =========
__global__ void prep_consts_kernel(const float* __restrict__ g2,
                                   const float* __restrict__ be2,
                                   const float* __restrict__ Wp,
                                   const float* __restrict__ bp)
{
    const int tid = threadIdx.x;
    float sg = 0.f, sb = 0.f;
    #pragma unroll
    for (int i = 0; i < 4; ++i) {
        int d = tid + i*256;
        float w = Wp[d];
        float gv = g2[d]*w;
        g_gw[d] = gv;
        sg += gv;
        sb += be2[d]*w;
    }
    __shared__ float r1[256], r2[256];
    r1[tid] = sg; r2[tid] = sb; __syncthreads();
    #pragma unroll
    for (int o = 128; o > 0; o >>= 1) {
        if (tid < o) { r1[tid] += r1[tid+o]; r2[tid] += r2[tid+o]; }
        __syncthreads();
    }
    if (tid == 0) { g_consts[0] = r1[0]; g_consts[1] = r2[0] + bp[0]; }
}

// ====== Kernel 3: HMMA split-bf16 GEMM + fused LN2-reduction epilogue ======
__device__ __forceinline__ void load_stage(uint32_t sb, int stage, int bm, int bn, int tid)
{
    const uint32_t st = sb + (uint32_t)(stage & 1) * STAGE_B;
    const int kbase = stage * KC;
    #pragma unroll
    for (int i = 0; i < 8; ++i) {
        const int id = i*256 + tid;
        const int isB = id >> 10;
        const int t = id & 1023;
        const int split = t >> 9, u = t & 511, r = u >> 2, seg = u & 3;
        const __nv_bfloat16* src;
        uint32_t dst;
        if (!isB) {
            src = (split ? g_Alo : g_Ahi) + (size_t)(bm + r)*DIM + kbase + seg*8;
            dst = st + (uint32_t)(split*SPLIT_B + r*ROWB + seg*16);
        } else {
            src = (split ? g_Blo : g_Bhi) + (size_t)(bn + r)*DIM + kbase + seg*8;
            dst = st + (uint32_t)(2*SPLIT_B + split*SPLIT_B + r*ROWB + seg*16);
        }
        cp16(dst, src);
    }
    asm volatile("cp.async.commit_group;" ::: "memory");
}

__global__ void __launch_bounds__(256, 2)
gemm_tc_kernel(const float* __restrict__ bias)
{
    extern __shared__ char sm_[];
    const uint32_t sb = s2u(sm_);
    const int tid = threadIdx.x, wid = tid >> 5, lane = tid & 31;
    const int bn = blockIdx.x * NT, bm = blockIdx.y * MT;
    const int wm = wid & 3, wn = wid >> 2;     // 4 M-groups x 2 N-groups

    float acc[2][8][4] = {};

    load_stage(sb, 0, bm, bn, tid);

    const uint32_t aOff = (uint32_t)((wm*32 + (lane & 15))*ROWB + (lane >> 4)*16);
    const uint32_t bOff = (uint32_t)(2*SPLIT_B
                       + (wn*64 + (lane & 7) + (lane >> 4)*8)*ROWB
                       + ((lane >> 3) & 1)*16);

    for (int s = 0; s < NSTAGE; ++s) {
        asm volatile("cp.async.wait_group 0;" ::: "memory");
        __syncthreads();
        if (s + 1 < NSTAGE) load_stage(sb, s + 1, bm, bn, tid);

        const uint32_t st = sb + (uint32_t)(s & 1) * STAGE_B;
        #pragma unroll
        for (int ks = 0; ks < 2; ++ks) {
            const uint32_t kb = (uint32_t)(ks*32);
            uint32_t Ah[2][4], Bh[4][4], T[4][4];
            #pragma unroll
            for (int mi = 0; mi < 2; ++mi)
                ldm4(Ah[mi], st + aOff + (uint32_t)(mi*16*ROWB) + kb);
            #pragma unroll
            for (int np = 0; np < 4; ++np)
                ldm4(Bh[np], st + bOff + (uint32_t)(np*16*ROWB) + kb);
            // hi*hi
            #pragma unroll
            for (int mi = 0; mi < 2; ++mi)
                #pragma unroll
                for (int ni = 0; ni < 8; ++ni)
                    mma16816(acc[mi][ni], Ah[mi], &Bh[ni>>1][(ni&1)*2]);
            // hi*lo (B_lo)
            #pragma unroll
            for (int np = 0; np < 4; ++np)
                ldm4(T[np], st + bOff + (uint32_t)(SPLIT_B + np*16*ROWB) + kb);
            #pragma unroll
            for (int mi = 0; mi < 2; ++mi)
                #pragma unroll
                for (int ni = 0; ni < 8; ++ni)
                    mma16816(acc[mi][ni], Ah[mi], &T[ni>>1][(ni&1)*2]);
            // lo*hi (A_lo)
            #pragma unroll
            for (int mi = 0; mi < 2; ++mi)
                ldm4(T[mi], st + aOff + (uint32_t)(SPLIT_B + mi*16*ROWB) + kb);
            #pragma unroll
            for (int mi = 0; mi < 2; ++mi)
                #pragma unroll
                for (int ni = 0; ni < 8; ++ni)
                    mma16816(acc[mi][ni], T[mi], &Bh[ni>>1][(ni&1)*2]);
        }
    }

    // ---- fused epilogue: per-row partial S1,S2,S3 over this CTA's 128 cols ----
    __syncthreads();                       // done with pipeline smem
    float* sred = (float*)sm_;             // [2 wn][128 rows][3]

    const int c2 = (lane & 3)*2;
    const int r4 = lane >> 2;
    float st1[2][2] = {}, st2[2][2] = {}, st3[2][2] = {};  // [mi][row 0/+8]
    #pragma unroll
    for (int ni = 0; ni < 8; ++ni) {
        const int n = bn + wn*64 + ni*8 + c2;
        const float2 bv = *(const float2*)(bias + n);
        const float2 gv = *(const float2*)(g_gw + n);
        #pragma unroll
        for (int mi = 0; mi < 2; ++mi) {
            float x0 = acc[mi][ni][0] + bv.x;
            float x1 = acc[mi][ni][1] + bv.y;
            float x2 = acc[mi][ni][2] + bv.x;
            float x3 = acc[mi][ni][3] + bv.y;
            st1[mi][0] += x0 + x1;           st1[mi][1] += x2 + x3;
            st2[mi][0] += x0*x0 + x1*x1;     st2[mi][1] += x2*x2 + x3*x3;
            st3[mi][0] += x0*gv.x + x1*gv.y; st3[mi][1] += x2*gv.x + x3*gv.y;
        }
    }
    // reduce over the 4 lanes sharing each row (lane = r4*4 + c)
    #pragma unroll
    for (int mi = 0; mi < 2; ++mi)
        #pragma unroll
        for (int h = 0; h < 2; ++h) {
            #pragma unroll
            for (int o = 1; o < 4; o <<= 1) {
                st1[mi][h] += __shfl_xor_sync(0xFFFFFFFFu, st1[mi][h], o);
                st2[mi][h] += __shfl_xor_sync(0xFFFFFFFFu, st2[mi][h], o);
                st3[mi][h] += __shfl_xor_sync(0xFFFFFFFFu, st3[mi][h], o);
            }
        }
    if ((lane & 3) == 0) {
        #pragma unroll
        for (int mi = 0; mi < 2; ++mi)
            #pragma unroll
            for (int h = 0; h < 2; ++h) {
                const int row = wm*32 + mi*16 + h*8 + r4;
                float* p = sred + (wn*128 + row)*3;
                p[0] = st1[mi][h]; p[1] = st2[mi][h]; p[2] = st3[mi][h];
            }
    }
    __syncthreads();
    if (tid < 128) {
        const int m = bm + tid;
        const int t = blockIdx.x;
        #pragma unroll
        for (int c = 0; c < 3; ++c)
            g_part[(c*8 + t)*MROWS + m] =
                sred[(0*128 + tid)*3 + c] + sred[(1*128 + tid)*3 + c];
    }
}

// ===== Kernel 4a: combine partials -> pred scalar per kept row =====
__global__ void combine_kernel()
{
    const int m = blockIdx.x*256 + threadIdx.x;
    if (m >= MROWS) return;
    float S1 = 0.f, S2 = 0.f, S3 = 0.f;
    #pragma unroll
    for (int t = 0; t < 8; ++t) {
        S1 += g_part[(0*8 + t)*MROWS + m];
        S2 += g_part[(1*8 + t)*MROWS + m];
        S3 += g_part[(2*8 + t)*MROWS + m];
    }
    const float mean = S1 * (1.0f/DIM);
    const float var  = S2 * (1.0f/DIM) - mean*mean;
    const float inv  = rsqrtf(var + LN_EPS);
    g_s[m] = inv*(S3 - mean*g_consts[0]) + g_consts[1];
}

// ===== Kernel 4b: mask_token pred =====
__global__ void mask_pred_kernel(const float* __restrict__ mask_token,
                                 const float* __restrict__ g2,
                                 const float* __restrict__ be2,
                                 const float* __restrict__ Wp,
                                 const float* __restrict__ bp)
{
    const int tid = threadIdx.x;
    float v[4];
    #pragma unroll
    for (int i = 0; i < 4; ++i) v[i] = mask_token[tid + i*256];

    __shared__ float red[256];
    float s = v[0]+v[1]+v[2]+v[3];
    red[tid] = s; __syncthreads();
    #pragma unroll
    for (int o = 128; o > 0; o >>= 1) { if (tid < o) red[tid] += red[tid+o]; __syncthreads(); }
    const float mean = red[0] * (1.0f/DIM);
    __syncthreads();
    float sv = 0.f;
    #pragma unroll
    for (int i = 0; i < 4; ++i) { float dv = v[i]-mean; sv += dv*dv; }
    red[tid] = sv; __syncthreads();
    #pragma unroll
    for (int o = 128; o > 0; o >>= 1) { if (tid < o) red[tid] += red[tid+o]; __syncthreads(); }
    const float inv = rsqrtf(red[0]*(1.0f/DIM) + LN_EPS);
    __syncthreads();
    float part = 0.f;
    #pragma unroll
    for (int i = 0; i < 4; ++i) {
        int d = tid + i*256;
        part += ((v[i]-mean)*inv*g2[d] + be2[d]) * Wp[d];
    }
    red[tid] = part; __syncthreads();
    #pragma unroll
    for (int o = 128; o > 0; o >>= 1) { if (tid < o) red[tid] += red[tid+o]; __syncthreads(); }
    if (tid == 0) g_s[MROWS] = red[0] + bp[0];
}

// ===== Kernel 5: scatter pred/mask + per-batch loss partial =====
__global__ void out_kernel(const float* __restrict__ expr,
                           float* __restrict__ out_pred,
                           float* __restrict__ out_mask)
{
    const int b = blockIdx.x;
    const float cm = g_s[MROWS];
    float part = 0.f;
    for (int l = threadIdx.x; l < LSEQ; l += blockDim.x) {
        const int r = g_rank[b*LSEQ + l];
        const bool masked = (r >= KEEP);
        const float p = masked ? cm : g_s[b*KEEP + r];
        out_pred[b*LSEQ + l] = p;
        out_mask[b*LSEQ + l] = masked ? 1.0f : 0.0f;
        if (masked) {
            float t = expr[b*LSEQ + l];
            if (isnan(t)) t = 0.f;
            const float d = p - t;
            part += d*d;
        }
    }
    __shared__ float red[256];
    red[threadIdx.x] = part; __syncthreads();
    #pragma unroll
    for (int o = 128; o > 0; o >>= 1) {
        if (threadIdx.x < o) red[threadIdx.x] += red[threadIdx.x+o];
        __syncthreads();
    }
    if (threadIdx.x == 0) g_losspart[b] = red[0];
}

// ===== Kernel 6: final loss =====
__global__ void loss_kernel(float* __restrict__ out)
{
    if (threadIdx.x == 0) {
        float s = 0.f;
        for (int i = 0; i < BATCH; ++i) s += g_losspart[i];
        out[0] = s / (float)NMASK;
    }
}

// =============================== launch ===============================
extern "C" void kernel_launch(void* const* d_in, const int* in_sizes, int n_in,
                              void* d_out, int out_size)
{
    const float* expr      = (const float*)d_in[0];
    const int*   idx       = (const int*)  d_in[1];
    const float* noise     = (const float*)d_in[2];
    const float* pos_table = (const float*)d_in[3];
    const float* cls_token = (const float*)d_in[4];
    const float* w_enc     = (const float*)d_in[5];
    const float* b_enc     = (const float*)d_in[6];
    const float* gamma1    = (const float*)d_in[7];
    const float* beta1     = (const float*)d_in[8];
    const float* W_dec     = (const float*)d_in[9];
    const float* b_dec     = (const float*)d_in[10];
    const float* mask_tok  = (const float*)d_in[11];
    const float* gamma2    = (const float*)d_in[12];
    const float* beta2     = (const float*)d_in[13];
    const float* W_pred    = (const float*)d_in[14];
    const float* b_pred    = (const float*)d_in[15];

    float* out = (float*)d_out;
    float* out_loss  = out;
    float* out_pred  = out + 1;
    float* out_mask  = out + 1 + BATCH*LSEQ;
    float* out_lat0  = out + 1 + 2*BATCH*LSEQ;

    cudaFuncSetAttribute(gemm_tc_kernel,
                         cudaFuncAttributeMaxDynamicSharedMemorySize, SMEM_TOTAL);

    prep_b_kernel<<<dim3(32, 32), dim3(32, 8)>>>(W_dec);
    prep_consts_kernel<<<1, 256>>>(gamma2, beta2, W_pred, b_pred);
    rank_kernel<<<dim3(BATCH, 8), 256>>>(noise);
    enc_ln_kernel<<<dim3(KEEP+1, BATCH), 256>>>(expr, idx, pos_table, cls_token,
                                                w_enc, b_enc, gamma1, beta1, out_lat0);
    gemm_tc_kernel<<<dim3(DIM/NT, MROWS/MT), 256, SMEM_TOTAL>>>(b_dec);
    mask_pred_kernel<<<1, 256>>>(mask_tok, gamma2, beta2, W_pred, b_pred);
    combine_kernel<<<(MROWS + 255)/256, 256>>>();
    out_kernel<<<BATCH, 256>>>(expr, out_pred, out_mask);
    loss_kernel<<<1, 32>>>(out_loss);
}

// round 6
// speedup vs baseline: 2.5645x; 1.0385x over previous
#include <cuda_runtime.h>
#include <cuda_bf16.h>
#include <math.h>
#include <stdint.h>

#define BATCH 32
#define LSEQ  2000
#define DIM   1024
#define KEEP  500
#define MROWS (BATCH*KEEP)           // 16000
#define NMASK (BATCH*(LSEQ-KEEP))    // 48000
#define LN_EPS 1e-5f

// GEMM tiling: CTA 128x128, warp 32x64 (4 M-groups x 2 N-groups), KC=32, 2 stages
#define MT 128
#define NT 128
#define KC 32
#define NSTAGE (DIM/KC)              // 32
#define NTILES ((MROWS/MT)*(DIM/NT)) // 1000
#define ROWB 80                      // padded smem row bytes
#define SPLIT_B (128*ROWB)           // 10240
#define STAGE_B (4*SPLIT_B)          // 40960 (Ahi,Alo,Bhi,Blo)
#define SMEM_TOTAL (2*STAGE_B)       // 81920
#define GEMM_GRID 296                // 2 CTAs/SM * 148 SMs (persistent)

// -------- scratch (device globals) --------
__device__ int   g_rank[BATCH*LSEQ];
__device__ int   g_keep[BATCH*KEEP];
__device__ __align__(16) __nv_bfloat16 g_Ahi[MROWS*DIM];
__device__ __align__(16) __nv_bfloat16 g_Alo[MROWS*DIM];
__device__ __align__(16) __nv_bfloat16 g_Bhi[DIM*DIM];   // [n][k] = W_dec[k][n]
__device__ __align__(16) __nv_bfloat16 g_Blo[DIM*DIM];
__device__ __align__(16) float g_gw[DIM];                // gamma2*W_pred
__device__ float g_consts[2];                            // {sum(g2*Wp), sum(be2*Wp)+bp}
__device__ float g_part[3*8*MROWS];                      // [stat][ntile][row]
__device__ float g_s[MROWS+1];
__device__ float g_losspart[BATCH];

// =============================== PTX helpers ===============================
__device__ __forceinline__ uint32_t s2u(const void* p) {
    uint32_t a;
    asm("{ .reg .u64 t; cvta.to.shared.u64 t, %1; cvt.u32.u64 %0, t; }" : "=r"(a) : "l"(p));
    return a;
}
__device__ __forceinline__ void cp16(uint32_t s, const void* g) {
    asm volatile("cp.async.cg.shared.global [%0], [%1], 16;" :: "r"(s), "l"(g) : "memory");
}
__device__ __forceinline__ void ldm4(uint32_t* r, uint32_t addr) {
    asm volatile("ldmatrix.sync.aligned.m8n8.x4.shared.b16 {%0,%1,%2,%3}, [%4];"
                 : "=r"(r[0]), "=r"(r[1]), "=r"(r[2]), "=r"(r[3]) : "r"(addr));
}
__device__ __forceinline__ void mma16816(float* c, const uint32_t* a, const uint32_t* b) {
    asm volatile(
        "mma.sync.aligned.m16n8k16.row.col.f32.bf16.bf16.f32 "
        "{%0,%1,%2,%3}, {%4,%5,%6,%7}, {%8,%9}, {%0,%1,%2,%3};"
        : "+f"(c[0]), "+f"(c[1]), "+f"(c[2]), "+f"(c[3])
        : "r"(a[0]), "r"(a[1]), "r"(a[2]), "r"(a[3]), "r"(b[0]), "r"(b[1]));
}

// ===================== Kernel 1: stable ranks of noise =====================
__global__ void rank_kernel(const float* __restrict__ noise)
{
    __shared__ float sh[LSEQ];
    const int b = blockIdx.x;
    const float* nrow = noise + b*LSEQ;
    for (int i = threadIdx.x; i < LSEQ; i += blockDim.x) sh[i] = nrow[i];
    __syncthreads();

    const int j = blockIdx.y*250 + threadIdx.x;
    if (threadIdx.x >= 250) return;
    const float nj = sh[j];
    int r = 0;
    #pragma unroll 4
    for (int k = 0; k < LSEQ; ++k) {
        float nk = sh[k];
        r += (nk < nj) || (nk == nj && k < j);
    }
    g_rank[b*LSEQ + j] = r;
    if (r < KEEP) g_keep[b*KEEP + r] = j;
}

// ===== Kernel 2: gather + encode + LayerNorm1 -> bf16 split A (+latent0) =====
__global__ void enc_ln_kernel(const float* __restrict__ expr,
                              const int*   __restrict__ idx,
                              const float* __restrict__ pos,
                              const float* __restrict__ cls,
                              const float* __restrict__ w_enc,
                              const float* __restrict__ b_enc,
                              const float* __restrict__ g1,
                              const float* __restrict__ be1,
                              float* __restrict__ out_lat0)
{
    const int t = blockIdx.x, b = blockIdx.y, tid = threadIdx.x;
    const int wrp = tid >> 5, lane = tid & 31;

    float4 v;
    if (t == 0) {
        float4 c = ((const float4*)cls)[tid];
        float4 p = ((const float4*)pos)[tid];
        v.x = c.x + p.x; v.y = c.y + p.y; v.z = c.z + p.z; v.w = c.w + p.w;
    } else {
        const int j = g_keep[b*KEEP + (t-1)];
        const float e = expr[b*LSEQ + j];
        const float4 p = ((const float4*)(pos + (size_t)idx[b*LSEQ + j]*DIM))[tid];
        const float4 w = ((const float4*)w_enc)[tid];
        const float4 bb = ((const float4*)b_enc)[tid];
        v.x = fmaf(e, w.x, bb.x) + p.x;
        v.y = fmaf(e, w.y, bb.y) + p.y;
        v.z = fmaf(e, w.z, bb.z) + p.z;
        v.w = fmaf(e, w.w, bb.w) + p.w;
    }

    float s  = v.x + v.y + v.z + v.w;
    float sq = v.x*v.x + v.y*v.y + v.z*v.z + v.w*v.w;
    #pragma unroll
    for (int o = 16; o; o >>= 1) {
        s  += __shfl_xor_sync(0xFFFFFFFFu, s,  o);
        sq += __shfl_xor_sync(0xFFFFFFFFu, sq, o);
    }
    __shared__ float ws[16];
    if (lane == 0) { ws[wrp] = s; ws[8 + wrp] = sq; }
    __syncthreads();
    float S = 0.f, SQ = 0.f;
    #pragma unroll
    for (int i = 0; i < 8; ++i) { S += ws[i]; SQ += ws[8 + i]; }
    const float mean = S * (1.0f/DIM);
    const float var  = SQ * (1.0f/DIM) - mean*mean;
    const float inv  = rsqrtf(var + LN_EPS);

    const float4 g  = ((const float4*)g1)[tid];
    const float4 be = ((const float4*)be1)[tid];
    float r0 = (v.x - mean)*inv*g.x + be.x;
    float r1 = (v.y - mean)*inv*g.y + be.y;
    float r2 = (v.z - mean)*inv*g.z + be.z;
    float r3 = (v.w - mean)*inv*g.w + be.w;

    if (t == 0) {
        // out_lat0 lives in d_out at a 4B-aligned (not 16B) offset: scalar stores only.
        float* dst = out_lat0 + b*DIM + tid*4;
        dst[0] = r0; dst[1] = r1; dst[2] = r2; dst[3] = r3;
    } else {
        const size_t row = (size_t)(b*KEEP + (t-1))*DIM;
        __nv_bfloat16 h0 = __float2bfloat16(r0), h1 = __float2bfloat16(r1);
        __nv_bfloat16 h2 = __float2bfloat16(r2), h3 = __float2bfloat16(r3);
        __nv_bfloat162 hA; hA.x = h0; hA.y = h1;
        __nv_bfloat162 hB; hB.x = h2; hB.y = h3;
        ((__nv_bfloat162*)(g_Ahi + row))[tid*2+0] = hA;
        ((__nv_bfloat162*)(g_Ahi + row))[tid*2+1] = hB;
        __nv_bfloat162 lA, lB;
        lA.x = __float2bfloat16(r0 - __bfloat162float(h0));
        lA.y = __float2bfloat16(r1 - __bfloat162float(h1));
        lB.x = __float2bfloat16(r2 - __bfloat162float(h2));
        lB.y = __float2bfloat16(r3 - __bfloat162float(h3));
        ((__nv_bfloat162*)(g_Alo + row))[tid*2+0] = lA;
        ((__nv_bfloat162*)(g_Alo + row))[tid*2+1] = lB;
    }
}

// ========= Kernel 2b: transpose + bf16-split W_dec =========
__global__ void prep_b_kernel(const float* __restrict__ Wd)
{
    __shared__ float t[32][33];
    const int tx = threadIdx.x, ty = threadIdx.y;
    const int bx = blockIdx.x, by = blockIdx.y;
    #pragma unroll
    for (int j = 0; j < 32; j += 8)
        t[ty+j][tx] = Wd[(size_t)(by*32 + ty + j)*DIM + bx*32 + tx];
    __syncthreads();
    #pragma unroll
    for (int j = 0; j < 32; j += 8) {
        float v = t[tx][ty+j];
        size_t o = (size_t)(bx*32 + ty + j)*DIM + by*32 + tx;  // [n][k]
        __nv_bfloat16 h = __float2bfloat16(v);
        g_Bhi[o] = h;
        g_Blo[o] = __float2bfloat16(v - __bfloat162float(h));
    }
}

// ========= Kernel 2c: gw = g2*Wp, consts =========
__global__ void prep_consts_kernel(const float* __restrict__ g2,
                                   const float* __restrict__ be2,
                                   const float* __restrict__ Wp,
                                   const float* __restrict__ bp)
{
    const int tid = threadIdx.x;
    float sg = 0.f, sb = 0.f;
    #pragma unroll
    for (int i = 0; i < 4; ++i) {
        int d = tid + i*256;
        float w = Wp[d];
        float gv = g2[d]*w;
        g_gw[d] = gv;
        sg += gv;
        sb += be2[d]*w;
    }
    __shared__ float r1[256], r2[256];
    r1[tid] = sg; r2[tid] = sb; __syncthreads();
    #pragma unroll
    for (int o = 128; o > 0; o >>= 1) {
        if (tid < o) { r1[tid] += r1[tid+o]; r2[tid] += r2[tid+o]; }
        __syncthreads();
    }
    if (tid == 0) { g_consts[0] = r1[0]; g_consts[1] = r2[0] + bp[0]; }
}

// ====== Kernel 3: persistent HMMA split-bf16 GEMM + fused LN2 epilogue ======
__device__ __forceinline__ void load_stage(uint32_t sb, int stage, int bm, int bn, int tid)
{
    const uint32_t st = sb + (uint32_t)(stage & 1) * STAGE_B;
    const int kbase = stage * KC;
    #pragma unroll
    for (int i = 0; i < 8; ++i) {
        const int id = i*256 + tid;
        const int isB = id >> 10;
        const int t = id & 1023;
        const int split = t >> 9, u = t & 511, r = u >> 2, seg = u & 3;
        const __nv_bfloat16* src;
        uint32_t dst;
        if (!isB) {
            src = (split ? g_Alo : g_Ahi) + (size_t)(bm + r)*DIM + kbase + seg*8;
            dst = st + (uint32_t)(split*SPLIT_B + r*ROWB + seg*16);
        } else {
            src = (split ? g_Blo : g_Bhi) + (size_t)(bn + r)*DIM + kbase + seg*8;
            dst = st + (uint32_t)(2*SPLIT_B + split*SPLIT_B + r*ROWB + seg*16);
        }
        cp16(dst, src);
    }
    asm volatile("cp.async.commit_group;" ::: "memory");
}

__global__ void __launch_bounds__(256, 2)
gemm_tc_kernel(const float* __restrict__ bias)
{
    extern __shared__ char sm_[];
    const uint32_t sb = s2u(sm_);
    const int tid = threadIdx.x, wid = tid >> 5, lane = tid & 31;
    const int wm = wid & 3, wn = wid >> 2;     // 4 M-groups x 2 N-groups

    const uint32_t aOff = (uint32_t)((wm*32 + (lane & 15))*ROWB + (lane >> 4)*16);
    const uint32_t bOff = (uint32_t)(2*SPLIT_B
                       + (wn*64 + (lane & 7) + (lane >> 4)*8)*ROWB
                       + ((lane >> 3) & 1)*16);
    const int c2 = (lane & 3)*2;
    const int r4 = lane >> 2;

    for (int tile = blockIdx.x; tile < NTILES; tile += GEMM_GRID) {
        const int bn = (tile & 7) * NT;
        const int bm = (tile >> 3) * MT;

        float acc[2][8][4] = {};
        __syncthreads();                 // smem free of prior tile's epilogue
        load_stage(sb, 0, bm, bn, tid);

        for (int s = 0; s < NSTAGE; ++s) {
            asm volatile("cp.async.wait_group 0;" ::: "memory");
            __syncthreads();
            if (s + 1 < NSTAGE) load_stage(sb, s + 1, bm, bn, tid);

            const uint32_t st = sb + (uint32_t)(s & 1) * STAGE_B;
            #pragma unroll
            for (int ks = 0; ks < 2; ++ks) {
                const uint32_t kb = (uint32_t)(ks*32);
                uint32_t Ah[2][4], Bh[4][4], T[4][4];
                #pragma unroll
                for (int mi = 0; mi < 2; ++mi)
                    ldm4(Ah[mi], st + aOff + (uint32_t)(mi*16*ROWB) + kb);
                #pragma unroll
                for (int np = 0; np < 4; ++np)
                    ldm4(Bh[np], st + bOff + (uint32_t)(np*16*ROWB) + kb);
                // hi*hi
                #pragma unroll
                for (int mi = 0; mi < 2; ++mi)
                    #pragma unroll
                    for (int ni = 0; ni < 8; ++ni)
                        mma16816(acc[mi][ni], Ah[mi], &Bh[ni>>1][(ni&1)*2]);
                // hi*lo (B_lo)
                #pragma unroll
                for (int np = 0; np < 4; ++np)
                    ldm4(T[np], st + bOff + (uint32_t)(SPLIT_B + np*16*ROWB) + kb);
                #pragma unroll
                for (int mi = 0; mi < 2; ++mi)
                    #pragma unroll
                    for (int ni = 0; ni < 8; ++ni)
                        mma16816(acc[mi][ni], Ah[mi], &T[ni>>1][(ni&1)*2]);
                // lo*hi (A_lo)
                #pragma unroll
                for (int mi = 0; mi < 2; ++mi)
                    ldm4(T[mi], st + aOff + (uint32_t)(SPLIT_B + mi*16*ROWB) + kb);
                #pragma unroll
                for (int mi = 0; mi < 2; ++mi)
                    #pragma unroll
                    for (int ni = 0; ni < 8; ++ni)
                        mma16816(acc[mi][ni], T[mi], &Bh[ni>>1][(ni&1)*2]);
            }
        }

        // ---- fused epilogue: per-row partial S1,S2,S3 over this CTA's 128 cols ----
        __syncthreads();
        float* sred = (float*)sm_;             // [2 wn][128 rows][3]

        float st1[2][2] = {}, st2[2][2] = {}, st3[2][2] = {};
        #pragma unroll
        for (int ni = 0; ni < 8; ++ni) {
            const int n = bn + wn*64 + ni*8 + c2;
            const float2 bv = *(const float2*)(bias + n);
            const float2 gv = *(const float2*)(g_gw + n);
            #pragma unroll
            for (int mi = 0; mi < 2; ++mi) {
                float x0 = acc[mi][ni][0] + bv.x;
                float x1 = acc[mi][ni][1] + bv.y;
                float x2 = acc[mi][ni][2] + bv.x;
                float x3 = acc[mi][ni][3] + bv.y;
                st1[mi][0] += x0 + x1;           st1[mi][1] += x2 + x3;
                st2[mi][0] += x0*x0 + x1*x1;     st2[mi][1] += x2*x2 + x3*x3;
                st3[mi][0] += x0*gv.x + x1*gv.y; st3[mi][1] += x2*gv.x + x3*gv.y;
            }
        }
        #pragma unroll
        for (int mi = 0; mi < 2; ++mi)
            #pragma unroll
            for (int h = 0; h < 2; ++h) {
                #pragma unroll
                for (int o = 1; o < 4; o <<= 1) {
                    st1[mi][h] += __shfl_xor_sync(0xFFFFFFFFu, st1[mi][h], o);
                    st2[mi][h] += __shfl_xor_sync(0xFFFFFFFFu, st2[mi][h], o);
                    st3[mi][h] += __shfl_xor_sync(0xFFFFFFFFu, st3[mi][h], o);
                }
            }
        if ((lane & 3) == 0) {
            #pragma unroll
            for (int mi = 0; mi < 2; ++mi)
                #pragma unroll
                for (int h = 0; h < 2; ++h) {
                    const int row = wm*32 + mi*16 + h*8 + r4;
                    float* p = sred + (wn*128 + row)*3;
                    p[0] = st1[mi][h]; p[1] = st2[mi][h]; p[2] = st3[mi][h];
                }
        }
        __syncthreads();
        if (tid < 128) {
            const int m = bm + tid;
            const int t8 = tile & 7;
            #pragma unroll
            for (int c = 0; c < 3; ++c)
                g_part[(c*8 + t8)*MROWS + m] =
                    sred[(0*128 + tid)*3 + c] + sred[(1*128 + tid)*3 + c];
        }
    }
}

// ===== Kernel 4a: combine partials -> pred scalar per kept row =====
__global__ void combine_kernel()
{
    const int m = blockIdx.x*256 + threadIdx.x;
    if (m >= MROWS) return;
    float S1 = 0.f, S2 = 0.f, S3 = 0.f;
    #pragma unroll
    for (int t = 0; t < 8; ++t) {
        S1 += g_part[(0*8 + t)*MROWS + m];
        S2 += g_part[(1*8 + t)*MROWS + m];
        S3 += g_part[(2*8 + t)*MROWS + m];
    }
    const float mean = S1 * (1.0f/DIM);
    const float var  = S2 * (1.0f/DIM) - mean*mean;
    const float inv  = rsqrtf(var + LN_EPS);
    g_s[m] = inv*(S3 - mean*g_consts[0]) + g_consts[1];
}

// ===== Kernel 4b: mask_token pred =====
__global__ void mask_pred_kernel(const float* __restrict__ mask_token,
                                 const float* __restrict__ g2,
                                 const float* __restrict__ be2,
                                 const float* __restrict__ Wp,
                                 const float* __restrict__ bp)
{
    const int tid = threadIdx.x;
    float v[4];
    #pragma unroll
    for (int i = 0; i < 4; ++i) v[i] = mask_token[tid + i*256];

    __shared__ float red[256];
    float s = v[0]+v[1]+v[2]+v[3];
    red[tid] = s; __syncthreads();
    #pragma unroll
    for (int o = 128; o > 0; o >>= 1) { if (tid < o) red[tid] += red[tid+o]; __syncthreads(); }
    const float mean = red[0] * (1.0f/DIM);
    __syncthreads();
    float sv = 0.f;
    #pragma unroll
    for (int i = 0; i < 4; ++i) { float dv = v[i]-mean; sv += dv*dv; }
    red[tid] = sv; __syncthreads();
    #pragma unroll
    for (int o = 128; o > 0; o >>= 1) { if (tid < o) red[tid] += red[tid+o]; __syncthreads(); }
    const float inv = rsqrtf(red[0]*(1.0f/DIM) + LN_EPS);
    __syncthreads();
    float part = 0.f;
    #pragma unroll
    for (int i = 0; i < 4; ++i) {
        int d = tid + i*256;
        part += ((v[i]-mean)*inv*g2[d] + be2[d]) * Wp[d];
    }
    red[tid] = part; __syncthreads();
    #pragma unroll
    for (int o = 128; o > 0; o >>= 1) { if (tid < o) red[tid] += red[tid+o]; __syncthreads(); }
    if (tid == 0) g_s[MROWS] = red[0] + bp[0];
}

// ===== Kernel 5: scatter pred/mask + per-batch loss partial =====
__global__ void out_kernel(const float* __restrict__ expr,
                           float* __restrict__ out_pred,
                           float* __restrict__ out_mask)
{
    const int b = blockIdx.x;
    const float cm = g_s[MROWS];
    float part = 0.f;
    for (int l = threadIdx.x; l < LSEQ; l += blockDim.x) {
        const int r = g_rank[b*LSEQ + l];
        const bool masked = (r >= KEEP);
        const float p = masked ? cm : g_s[b*KEEP + r];
        out_pred[b*LSEQ + l] = p;
        out_mask[b*LSEQ + l] = masked ? 1.0f : 0.0f;
        if (masked) {
            float t = expr[b*LSEQ + l];
            if (isnan(t)) t = 0.f;
            const float d = p - t;
            part += d*d;
        }
    }
    __shared__ float red[256];
    red[threadIdx.x] = part; __syncthreads();
    #pragma unroll
    for (int o = 128; o > 0; o >>= 1) {
        if (threadIdx.x < o) red[threadIdx.x] += red[threadIdx.x+o];
        __syncthreads();
    }
    if (threadIdx.x == 0) g_losspart[b] = red[0];
}

// ===== Kernel 6: final loss =====
__global__ void loss_kernel(float* __restrict__ out)
{
    if (threadIdx.x == 0) {
        float s = 0.f;
        for (int i = 0; i < BATCH; ++i) s += g_losspart[i];
        out[0] = s / (float)NMASK;
    }
}

// =============================== launch ===============================
extern "C" void kernel_launch(void* const* d_in, const int* in_sizes, int n_in,
                              void* d_out, int out_size)
{
    const float* expr      = (const float*)d_in[0];
    const int*   idx       = (const int*)  d_in[1];
    const float* noise     = (const float*)d_in[2];
    const float* pos_table = (const float*)d_in[3];
    const float* cls_token = (const float*)d_in[4];
    const float* w_enc     = (const float*)d_in[5];
    const float* b_enc     = (const float*)d_in[6];
    const float* gamma1    = (const float*)d_in[7];
    const float* beta1     = (const float*)d_in[8];
    const float* W_dec     = (const float*)d_in[9];
    const float* b_dec     = (const float*)d_in[10];
    const float* mask_tok  = (const float*)d_in[11];
    const float* gamma2    = (const float*)d_in[12];
    const float* beta2     = (const float*)d_in[13];
    const float* W_pred    = (const float*)d_in[14];
    const float* b_pred    = (const float*)d_in[15];

    float* out = (float*)d_out;
    float* out_loss  = out;
    float* out_pred  = out + 1;
    float* out_mask  = out + 1 + BATCH*LSEQ;
    float* out_lat0  = out + 1 + 2*BATCH*LSEQ;

    cudaFuncSetAttribute(gemm_tc_kernel,
                         cudaFuncAttributeMaxDynamicSharedMemorySize, SMEM_TOTAL);

    prep_b_kernel<<<dim3(32, 32), dim3(32, 8)>>>(W_dec);
    prep_consts_kernel<<<1, 256>>>(gamma2, beta2, W_pred, b_pred);
    rank_kernel<<<dim3(BATCH, 8), 256>>>(noise);
    enc_ln_kernel<<<dim3(KEEP+1, BATCH), 256>>>(expr, idx, pos_table, cls_token,
                                                w_enc, b_enc, gamma1, beta1, out_lat0);
    gemm_tc_kernel<<<GEMM_GRID, 256, SMEM_TOTAL>>>(b_dec);
    mask_pred_kernel<<<1, 256>>>(mask_tok, gamma2, beta2, W_pred, b_pred);
    combine_kernel<<<(MROWS + 255)/256, 256>>>();
    out_kernel<<<BATCH, 256>>>(expr, out_pred, out_mask);
    loss_kernel<<<1, 32>>>(out_loss);
}

// round 7
// speedup vs baseline: 2.6548x; 1.0352x over previous
#include <cuda_runtime.h>
#include <cuda_bf16.h>
#include <math.h>
#include <stdint.h>

#define BATCH 32
#define LSEQ  2000
#define DIM   1024
#define KEEP  500
#define MROWS (BATCH*KEEP)           // 16000
#define NMASK (BATCH*(LSEQ-KEEP))    // 48000
#define LN_EPS 1e-5f

// GEMM tiling: CTA 128x128 with 4 warps of 64x64, KC=32, 2 stages, persistent
#define MT 128
#define NT 128
#define KC 32
#define NSTAGE (DIM/KC)              // 32
#define NTILES ((MROWS/MT)*(DIM/NT)) // 1000
#define ROWB 80                      // padded smem row bytes
#define SPLIT_B (128*ROWB)           // 10240
#define STAGE_B (4*SPLIT_B)          // 40960 (Ahi,Alo,Bhi,Blo)
#define SMEM_TOTAL (2*STAGE_B)       // 81920
#define GEMM_GRID 296                // 2 CTAs/SM * 148 SMs (persistent)

// -------- scratch (device globals) --------
__device__ int   g_rank[BATCH*LSEQ];
__device__ int   g_keep[BATCH*KEEP];
__device__ __align__(16) __nv_bfloat16 g_Ahi[MROWS*DIM];
__device__ __align__(16) __nv_bfloat16 g_Alo[MROWS*DIM];
__device__ __align__(16) __nv_bfloat16 g_Bhi[DIM*DIM];   // [n][k] = W_dec[k][n]
__device__ __align__(16) __nv_bfloat16 g_Blo[DIM*DIM];
__device__ __align__(16) float g_gw[DIM];                // gamma2*W_pred
__device__ float g_consts[2];                            // {sum(g2*Wp), sum(be2*Wp)+bp}
__device__ float g_part[3*8*MROWS];                      // [stat][ntile][row]
__device__ float g_s[MROWS+1];
__device__ float g_losspart[BATCH];

// =============================== PTX helpers ===============================
__device__ __forceinline__ uint32_t s2u(const void* p) {
    uint32_t a;
    asm("{ .reg .u64 t; cvta.to.shared.u64 t, %1; cvt.u32.u64 %0, t; }" : "=r"(a) : "l"(p));
    return a;
}
__device__ __forceinline__ void cp16(uint32_t s, const void* g) {
    asm volatile("cp.async.cg.shared.global [%0], [%1], 16;" :: "r"(s), "l"(g) : "memory");
}
__device__ __forceinline__ void ldm4(uint32_t* r, uint32_t addr) {
    asm volatile("ldmatrix.sync.aligned.m8n8.x4.shared.b16 {%0,%1,%2,%3}, [%4];"
                 : "=r"(r[0]), "=r"(r[1]), "=r"(r[2]), "=r"(r[3]) : "r"(addr));
}
__device__ __forceinline__ void mma16816(float* c, const uint32_t* a, const uint32_t* b) {
    asm volatile(
        "mma.sync.aligned.m16n8k16.row.col.f32.bf16.bf16.f32 "
        "{%0,%1,%2,%3}, {%4,%5,%6,%7}, {%8,%9}, {%0,%1,%2,%3};"
        : "+f"(c[0]), "+f"(c[1]), "+f"(c[2]), "+f"(c[3])
        : "r"(a[0]), "r"(a[1]), "r"(a[2]), "r"(a[3]), "r"(b[0]), "r"(b[1]));
}

// ===== Kernel 1 (fused setup): rank (256 blocks) + prep_b (1024) + consts (1) =====
__global__ void setup_kernel(const float* __restrict__ noise,
                             const float* __restrict__ Wd,
                             const float* __restrict__ g2,
                             const float* __restrict__ be2,
                             const float* __restrict__ Wp,
                             const float* __restrict__ bp)
{
    __shared__ float sh[LSEQ];
    const int bid = blockIdx.x, tid = threadIdx.x;

    if (bid < 256) {
        // ---- stable ranks of noise: block = (b, seg) ----
        const int b = bid >> 3, seg = bid & 7;
        const float* nrow = noise + b*LSEQ;
        for (int i = tid; i < LSEQ; i += 256) sh[i] = nrow[i];
        __syncthreads();
        const int j = seg*250 + tid;
        if (tid >= 250) return;
        const float nj = sh[j];
        int r = 0;
        #pragma unroll 4
        for (int k = 0; k < LSEQ; ++k) {
            float nk = sh[k];
            r += (nk < nj) || (nk == nj && k < j);
        }
        g_rank[b*LSEQ + j] = r;
        if (r < KEEP) g_keep[b*KEEP + r] = j;
    } else if (bid < 1280) {
        // ---- transpose + bf16-split W_dec ----
        const int bb = bid - 256, bx = bb & 31, by = bb >> 5;
        float (*t)[33] = (float(*)[33])sh;
        const int tx = tid & 31, ty = tid >> 5;   // ty 0..7
        #pragma unroll
        for (int j = 0; j < 32; j += 8)
            t[ty+j][tx] = Wd[(size_t)(by*32 + ty + j)*DIM + bx*32 + tx];
        __syncthreads();
        #pragma unroll
        for (int j = 0; j < 32; j += 8) {
            float v = t[tx][ty+j];
            size_t o = (size_t)(bx*32 + ty + j)*DIM + by*32 + tx;  // [n][k]
            __nv_bfloat16 h = __float2bfloat16(v);
            g_Bhi[o] = h;
            g_Blo[o] = __float2bfloat16(v - __bfloat162float(h));
        }
    } else {
        // ---- gw = g2*Wp, consts ----
        float sg = 0.f, sb = 0.f;
        #pragma unroll
        for (int i = 0; i < 4; ++i) {
            int d = tid + i*256;
            float w = Wp[d];
            float gv = g2[d]*w;
            g_gw[d] = gv;
            sg += gv;
            sb += be2[d]*w;
        }
        float* r1 = sh; float* r2 = sh + 256;
        r1[tid] = sg; r2[tid] = sb; __syncthreads();
        #pragma unroll
        for (int o = 128; o > 0; o >>= 1) {
            if (tid < o) { r1[tid] += r1[tid+o]; r2[tid] += r2[tid+o]; }
            __syncthreads();
        }
        if (tid == 0) { g_consts[0] = r1[0]; g_consts[1] = r2[0] + bp[0]; }
    }
}

// ===== Kernel 2: gather + encode + LN1 -> bf16 split A (+latent0), warp/row =====
__global__ void enc_ln_kernel(const float* __restrict__ expr,
                              const int*   __restrict__ idx,
                              const float* __restrict__ pos,
                              const float* __restrict__ cls,
                              const float* __restrict__ w_enc,
                              const float* __restrict__ b_enc,
                              const float* __restrict__ g1,
                              const float* __restrict__ be1,
                              float* __restrict__ out_lat0)
{
    const int g = blockIdx.x*8 + (threadIdx.x >> 5);   // 0..16031
    const int lane = threadIdx.x & 31;
    const int b = g / (KEEP+1);
    const int tt = g - b*(KEEP+1);                     // 0 = cls row

    float4 v[8];
    if (tt == 0) {
        #pragma unroll
        for (int i = 0; i < 8; ++i) {
            const int e4 = lane + i*32;
            float4 c = ((const float4*)cls)[e4];
            float4 p = ((const float4*)pos)[e4];
            v[i].x = c.x + p.x; v[i].y = c.y + p.y;
            v[i].z = c.z + p.z; v[i].w = c.w + p.w;
        }
    } else {
        const int j = g_keep[b*KEEP + tt - 1];
        const float e = expr[b*LSEQ + j];
        const float* prow = pos + (size_t)idx[b*LSEQ + j]*DIM;
        #pragma unroll
        for (int i = 0; i < 8; ++i) {
            const int e4 = lane + i*32;
            float4 p  = ((const float4*)prow)[e4];
            float4 w  = ((const float4*)w_enc)[e4];
            float4 bb = ((const float4*)b_enc)[e4];
            v[i].x = fmaf(e, w.x, bb.x) + p.x;
            v[i].y = fmaf(e, w.y, bb.y) + p.y;
            v[i].z = fmaf(e, w.z, bb.z) + p.z;
            v[i].w = fmaf(e, w.w, bb.w) + p.w;
        }
    }

    float s = 0.f, sq = 0.f;
    #pragma unroll
    for (int i = 0; i < 8; ++i) {
        s  += v[i].x + v[i].y + v[i].z + v[i].w;
        sq += v[i].x*v[i].x + v[i].y*v[i].y + v[i].z*v[i].z + v[i].w*v[i].w;
    }
    #pragma unroll
    for (int o = 16; o; o >>= 1) {
        s  += __shfl_xor_sync(0xFFFFFFFFu, s,  o);
        sq += __shfl_xor_sync(0xFFFFFFFFu, sq, o);
    }
    const float mean = s * (1.0f/DIM);
    const float var  = sq * (1.0f/DIM) - mean*mean;
    const float inv  = rsqrtf(var + LN_EPS);

    if (tt == 0) {
        // out_lat0 is only 4B-aligned inside d_out: scalar stores (32 warps total)
        float* dst = out_lat0 + b*DIM;
        #pragma unroll
        for (int i = 0; i < 8; ++i) {
            const int e4 = lane + i*32;
            const float4 gg = ((const float4*)g1)[e4];
            const float4 be = ((const float4*)be1)[e4];
            dst[e4*4+0] = (v[i].x - mean)*inv*gg.x + be.x;
            dst[e4*4+1] = (v[i].y - mean)*inv*gg.y + be.y;
            dst[e4*4+2] = (v[i].z - mean)*inv*gg.z + be.z;
            dst[e4*4+3] = (v[i].w - mean)*inv*gg.w + be.w;
        }
    } else {
        const size_t row = (size_t)(b*KEEP + tt - 1)*DIM;
        #pragma unroll
        for (int i = 0; i < 8; ++i) {
            const int e4 = lane + i*32;
            const float4 gg = ((const float4*)g1)[e4];
            const float4 be = ((const float4*)be1)[e4];
            float r0 = (v[i].x - mean)*inv*gg.x + be.x;
            float r1 = (v[i].y - mean)*inv*gg.y + be.y;
            float r2 = (v[i].z - mean)*inv*gg.z + be.z;
            float r3 = (v[i].w - mean)*inv*gg.w + be.w;
            __nv_bfloat16 h0 = __float2bfloat16(r0), h1 = __float2bfloat16(r1);
            __nv_bfloat16 h2 = __float2bfloat16(r2), h3 = __float2bfloat16(r3);
            __nv_bfloat162 hA; hA.x = h0; hA.y = h1;
            __nv_bfloat162 hB; hB.x = h2; hB.y = h3;
            ((__nv_bfloat162*)(g_Ahi + row))[e4*2+0] = hA;
            ((__nv_bfloat162*)(g_Ahi + row))[e4*2+1] = hB;
            __nv_bfloat162 lA, lB;
            lA.x = __float2bfloat16(r0 - __bfloat162float(h0));
            lA.y = __float2bfloat16(r1 - __bfloat162float(h1));
            lB.x = __float2bfloat16(r2 - __bfloat162float(h2));
            lB.y = __float2bfloat16(r3 - __bfloat162float(h3));
            ((__nv_bfloat162*)(g_Alo + row))[e4*2+0] = lA;
            ((__nv_bfloat162*)(g_Alo + row))[e4*2+1] = lB;
        }
    }
}

// ====== Kernel 3: persistent HMMA split-bf16 GEMM, 64x64 warp tiles ======
__device__ __forceinline__ void load_stage(uint32_t sb, int stage, int bm, int bn, int tid)
{
    const uint32_t st = sb + (uint32_t)(stage & 1) * STAGE_B;
    const int kbase = stage * KC;
    #pragma unroll
    for (int i = 0; i < 16; ++i) {
        const int id = i*128 + tid;           // 0..2047
        const int isB = id >> 10;
        const int t = id & 1023;
        const int split = t >> 9, u = t & 511, r = u >> 2, seg = u & 3;
        const __nv_bfloat16* src;
        uint32_t dst;
        if (!isB) {
            src = (split ? g_Alo : g_Ahi) + (size_t)(bm + r)*DIM + kbase + seg*8;
            dst = st + (uint32_t)(split*SPLIT_B + r*ROWB + seg*16);
        } else {
            src = (split ? g_Blo : g_Bhi) + (size_t)(bn + r)*DIM + kbase + seg*8;
            dst = st + (uint32_t)(2*SPLIT_B + split*SPLIT_B + r*ROWB + seg*16);
        }
        cp16(dst, src);
    }
    asm volatile("cp.async.commit_group;" ::: "memory");
}

__global__ void __launch_bounds__(128, 2)
gemm_tc_kernel(const float* __restrict__ bias)
{
    extern __shared__ char sm_[];
    const uint32_t sb = s2u(sm_);
    const int tid = threadIdx.x, wid = tid >> 5, lane = tid & 31;
    const int wm = wid & 1, wn = wid >> 1;     // 2x2 warps of 64x64

    const uint32_t aOff = (uint32_t)((wm*64 + (lane & 15))*ROWB + (lane >> 4)*16);
    const uint32_t bOff = (uint32_t)(2*SPLIT_B
                       + (wn*64 + (lane & 7) + (lane >> 4)*8)*ROWB
                       + ((lane >> 3) & 1)*16);
    const int c2 = (lane & 3)*2;
    const int r4 = lane >> 2;

    for (int tile = blockIdx.x; tile < NTILES; tile += GEMM_GRID) {
        const int bn = (tile & 7) * NT;
        const int bm = (tile >> 3) * MT;

        float acc[4][8][4] = {};
        __syncthreads();                 // smem free of prior tile's epilogue
        load_stage(sb, 0, bm, bn, tid);

        for (int s = 0; s < NSTAGE; ++s) {
            asm volatile("cp.async.wait_group 0;" ::: "memory");
            __syncthreads();
            if (s + 1 < NSTAGE) load_stage(sb, s + 1, bm, bn, tid);

            const uint32_t st = sb + (uint32_t)(s & 1) * STAGE_B;
            #pragma unroll
            for (int ks = 0; ks < 2; ++ks) {
                const uint32_t kb = (uint32_t)(ks*32);
                uint32_t Ah[4][4], Bh[4][4], T[4][4];
                #pragma unroll
                for (int mi = 0; mi < 4; ++mi)
                    ldm4(Ah[mi], st + aOff + (uint32_t)(mi*16*ROWB) + kb);
                #pragma unroll
                for (int np = 0; np < 4; ++np)
                    ldm4(Bh[np], st + bOff + (uint32_t)(np*16*ROWB) + kb);
                // hi*hi
                #pragma unroll
                for (int mi = 0; mi < 4; ++mi)
                    #pragma unroll
                    for (int ni = 0; ni < 8; ++ni)
                        mma16816(acc[mi][ni], Ah[mi], &Bh[ni>>1][(ni&1)*2]);
                // hi*lo (B_lo)
                #pragma unroll
                for (int np = 0; np < 4; ++np)
                    ldm4(T[np], st + bOff + (uint32_t)(SPLIT_B + np*16*ROWB) + kb);
                #pragma unroll
                for (int mi = 0; mi < 4; ++mi)
                    #pragma unroll
                    for (int ni = 0; ni < 8; ++ni)
                        mma16816(acc[mi][ni], Ah[mi], &T[ni>>1][(ni&1)*2]);
                // lo*hi (A_lo)
                #pragma unroll
                for (int mi = 0; mi < 4; ++mi)
                    ldm4(T[mi], st + aOff + (uint32_t)(SPLIT_B + mi*16*ROWB) + kb);
                #pragma unroll
                for (int mi = 0; mi < 4; ++mi)
                    #pragma unroll
                    for (int ni = 0; ni < 8; ++ni)
                        mma16816(acc[mi][ni], T[mi], &Bh[ni>>1][(ni&1)*2]);
            }
        }

        // ---- fused epilogue: per-row partial S1,S2,S3 over this CTA's 128 cols ----
        __syncthreads();
        float* sred = (float*)sm_;             // [2 wn][128 rows][3]

        float st1[4][2] = {}, st2[4][2] = {}, st3[4][2] = {};
        #pragma unroll
        for (int ni = 0; ni < 8; ++ni) {
            const int n = bn + wn*64 + ni*8 + c2;
            const float2 bv = *(const float2*)(bias + n);
            const float2 gv = *(const float2*)(g_gw + n);
            #pragma unroll
            for (int mi = 0; mi < 4; ++mi) {
                float x0 = acc[mi][ni][0] + bv.x;
                float x1 = acc[mi][ni][1] + bv.y;
                float x2 = acc[mi][ni][2] + bv.x;
                float x3 = acc[mi][ni][3] + bv.y;
                st1[mi][0] += x0 + x1;           st1[mi][1] += x2 + x3;
                st2[mi][0] += x0*x0 + x1*x1;     st2[mi][1] += x2*x2 + x3*x3;
                st3[mi][0] += x0*gv.x + x1*gv.y; st3[mi][1] += x2*gv.x + x3*gv.y;
            }
        }
        #pragma unroll
        for (int mi = 0; mi < 4; ++mi)
            #pragma unroll
            for (int h = 0; h < 2; ++h) {
                #pragma unroll
                for (int o = 1; o < 4; o <<= 1) {
                    st1[mi][h] += __shfl_xor_sync(0xFFFFFFFFu, st1[mi][h], o);
                    st2[mi][h] += __shfl_xor_sync(0xFFFFFFFFu, st2[mi][h], o);
                    st3[mi][h] += __shfl_xor_sync(0xFFFFFFFFu, st3[mi][h], o);
                }
            }
        if ((lane & 3) == 0) {
            #pragma unroll
            for (int mi = 0; mi < 4; ++mi)
                #pragma unroll
                for (int h = 0; h < 2; ++h) {
                    const int row = wm*64 + mi*16 + h*8 + r4;
                    float* p = sred + (wn*128 + row)*3;
                    p[0] = st1[mi][h]; p[1] = st2[mi][h]; p[2] = st3[mi][h];
                }
        }
        __syncthreads();
        {
            const int m = bm + tid;
            const int t8 = tile & 7;
            #pragma unroll
            for (int c = 0; c < 3; ++c)
                g_part[(c*8 + t8)*MROWS + m] =
                    sred[(0*128 + tid)*3 + c] + sred[(1*128 + tid)*3 + c];
        }
    }
}

// ===== Kernel 4 (fused): combine partials (blocks 0..62) + mask_token pred (63) =====
__global__ void combine_mask_kernel(const float* __restrict__ mask_token,
                                    const float* __restrict__ g2,
                                    const float* __restrict__ be2,
                                    const float* __restrict__ Wp,
                                    const float* __restrict__ bp)
{
    const int tid = threadIdx.x;
    if (blockIdx.x < 63) {
        const int m = blockIdx.x*256 + tid;
        if (m >= MROWS) return;
        float S1 = 0.f, S2 = 0.f, S3 = 0.f;
        #pragma unroll
        for (int t = 0; t < 8; ++t) {
            S1 += g_part[(0*8 + t)*MROWS + m];
            S2 += g_part[(1*8 + t)*MROWS + m];
            S3 += g_part[(2*8 + t)*MROWS + m];
        }
        const float mean = S1 * (1.0f/DIM);
        const float var  = S2 * (1.0f/DIM) - mean*mean;
        const float inv  = rsqrtf(var + LN_EPS);
        g_s[m] = inv*(S3 - mean*g_consts[0]) + g_consts[1];
    } else {
        float v[4];
        #pragma unroll
        for (int i = 0; i < 4; ++i) v[i] = mask_token[tid + i*256];

        __shared__ float red[256];
        float s = v[0]+v[1]+v[2]+v[3];
        red[tid] = s; __syncthreads();
        #pragma unroll
        for (int o = 128; o > 0; o >>= 1) { if (tid < o) red[tid] += red[tid+o]; __syncthreads(); }
        const float mean = red[0] * (1.0f/DIM);
        __syncthreads();
        float sv = 0.f;
        #pragma unroll
        for (int i = 0; i < 4; ++i) { float dv = v[i]-mean; sv += dv*dv; }
        red[tid] = sv; __syncthreads();
        #pragma unroll
        for (int o = 128; o > 0; o >>= 1) { if (tid < o) red[tid] += red[tid+o]; __syncthreads(); }
        const float inv = rsqrtf(red[0]*(1.0f/DIM) + LN_EPS);
        __syncthreads();
        float part = 0.f;
        #pragma unroll
        for (int i = 0; i < 4; ++i) {
            int d = tid + i*256;
            part += ((v[i]-mean)*inv*g2[d] + be2[d]) * Wp[d];
        }
        red[tid] = part; __syncthreads();
        #pragma unroll
        for (int o = 128; o > 0; o >>= 1) { if (tid < o) red[tid] += red[tid+o]; __syncthreads(); }
        if (tid == 0) g_s[MROWS] = red[0] + bp[0];
    }
}

// ===== Kernel 5: scatter pred/mask + per-batch loss partial =====
__global__ void out_kernel(const float* __restrict__ expr,
                           float* __restrict__ out_pred,
                           float* __restrict__ out_mask)
{
    const int b = blockIdx.x;
    const float cm = g_s[MROWS];
    float part = 0.f;
    for (int l = threadIdx.x; l < LSEQ; l += blockDim.x) {
        const int r = g_rank[b*LSEQ + l];
        const bool masked = (r >= KEEP);
        const float p = masked ? cm : g_s[b*KEEP + r];
        out_pred[b*LSEQ + l] = p;
        out_mask[b*LSEQ + l] = masked ? 1.0f : 0.0f;
        if (masked) {
            float t = expr[b*LSEQ + l];
            if (isnan(t)) t = 0.f;
            const float d = p - t;
            part += d*d;
        }
    }
    __shared__ float red[256];
    red[threadIdx.x] = part; __syncthreads();
    #pragma unroll
    for (int o = 128; o > 0; o >>= 1) {
        if (threadIdx.x < o) red[threadIdx.x] += red[threadIdx.x+o];
        __syncthreads();
    }
    if (threadIdx.x == 0) g_losspart[b] = red[0];
}

// ===== Kernel 6: final loss =====
__global__ void loss_kernel(float* __restrict__ out)
{
    if (threadIdx.x == 0) {
        float s = 0.f;
        for (int i = 0; i < BATCH; ++i) s += g_losspart[i];
        out[0] = s / (float)NMASK;
    }
}

// =============================== launch ===============================
extern "C" void kernel_launch(void* const* d_in, const int* in_sizes, int n_in,
                              void* d_out, int out_size)
{
    const float* expr      = (const float*)d_in[0];
    const int*   idx       = (const int*)  d_in[1];
    const float* noise     = (const float*)d_in[2];
    const float* pos_table = (const float*)d_in[3];
    const float* cls_token = (const float*)d_in[4];
    const float* w_enc     = (const float*)d_in[5];
    const float* b_enc     = (const float*)d_in[6];
    const float* gamma1    = (const float*)d_in[7];
    const float* beta1     = (const float*)d_in[8];
    const float* W_dec     = (const float*)d_in[9];
    const float* b_dec     = (const float*)d_in[10];
    const float* mask_tok  = (const float*)d_in[11];
    const float* gamma2    = (const float*)d_in[12];
    const float* beta2     = (const float*)d_in[13];
    const float* W_pred    = (const float*)d_in[14];
    const float* b_pred    = (const float*)d_in[15];

    float* out = (float*)d_out;
    float* out_loss  = out;
    float* out_pred  = out + 1;
    float* out_mask  = out + 1 + BATCH*LSEQ;
    float* out_lat0  = out + 1 + 2*BATCH*LSEQ;

    cudaFuncSetAttribute(gemm_tc_kernel,
                         cudaFuncAttributeMaxDynamicSharedMemorySize, SMEM_TOTAL);

    setup_kernel<<<1281, 256>>>(noise, W_dec, gamma2, beta2, W_pred, b_pred);
    enc_ln_kernel<<<(BATCH*(KEEP+1))/8, 256>>>(expr, idx, pos_table, cls_token,
                                               w_enc, b_enc, gamma1, beta1, out_lat0);
    gemm_tc_kernel<<<GEMM_GRID, 128, SMEM_TOTAL>>>(b_dec);
    combine_mask_kernel<<<64, 256>>>(mask_tok, gamma2, beta2, W_pred, b_pred);
    out_kernel<<<BATCH, 256>>>(expr, out_pred, out_mask);
    loss_kernel<<<1, 32>>>(out_loss);
}